// round 15
// baseline (speedup 1.0000x reference)
#include <cuda_runtime.h>
#include <cuda_bf16.h>
#include <math.h>

#define B_    4
#define E_    50
#define C_    64
#define HW_   2048
#define BE_   200
#define SLAB_ 131072      // C_*HW_
#define NTOT_ 26214400    // BE_*SLAB_
#define SB_   72          // bf16 smem row stride, 64 cols (LDSM conflict-free)
#define SD_   136         // bf16 smem row stride, 128 cols (LDSM conflict-free)

typedef unsigned int uint32;
typedef __nv_bfloat16 bf16;
typedef __nv_bfloat162 bf162;

// ---- scratch (static device globals; no allocation) ----
__device__ bf16 g_v[NTOT_];   // [b][c][e][hw]
__device__ bf16 g_k[NTOT_];   // [b][c][e][hw]
__device__ bf16 g_q[NTOT_];   // [b][c][e][hw]
__device__ bf16 g_t[NTOT_];   // [b][e][c][hw]
__device__ float g_wts[B_ * C_ * E_ * E_];       // w' = softmax - 1/E
__device__ float g_part[B_ * C_ * 4 * 64 * 64];  // gram partials per z (stride 64)
__device__ unsigned g_cnt[B_ * C_];              // last-block-done counters (self-reset)
__device__ float g_mu[BE_];
__device__ float g_rs[BE_];
__device__ bf16 g_wb[6 * 4096];   // bf16 weights: Wv,Wk,Wq,Wo,Wm1,Wm2 [o][c]
__device__ bf16 g_lng[SLAB_];
__device__ bf16 g_lnb[SLAB_];

// m16n8k16 bf16 mma, fp32 accumulate
__device__ __forceinline__ void mma16(float d[4], uint32 a0, uint32 a1, uint32 a2, uint32 a3,
                                      uint32 b0, uint32 b1) {
    asm volatile(
        "mma.sync.aligned.m16n8k16.row.col.f32.bf16.bf16.f32 "
        "{%0,%1,%2,%3}, {%4,%5,%6,%7}, {%8,%9}, {%0,%1,%2,%3};"
        : "+f"(d[0]), "+f"(d[1]), "+f"(d[2]), "+f"(d[3])
        : "r"(a0), "r"(a1), "r"(a2), "r"(a3), "r"(b0), "r"(b1));
}

__device__ __forceinline__ uint32 cvta_smem(const void* p) {
    return (uint32)__cvta_generic_to_shared(p);
}
__device__ __forceinline__ void ldsm4(uint32& r0, uint32& r1, uint32& r2, uint32& r3, uint32 a) {
    asm volatile("ldmatrix.sync.aligned.m8n8.x4.shared.b16 {%0,%1,%2,%3}, [%4];"
                 : "=r"(r0), "=r"(r1), "=r"(r2), "=r"(r3) : "r"(a));
}
__device__ __forceinline__ void ldsm4t(uint32& r0, uint32& r1, uint32& r2, uint32& r3, uint32 a) {
    asm volatile("ldmatrix.sync.aligned.m8n8.x4.trans.shared.b16 {%0,%1,%2,%3}, [%4];"
                 : "=r"(r0), "=r"(r1), "=r"(r2), "=r"(r3) : "r"(a));
}
__device__ __forceinline__ void cp16(uint32 dst, const void* src) {
    asm volatile("cp.async.cg.shared.global [%0], [%1], 16;" :: "r"(dst), "l"(src));
}
__device__ __forceinline__ void cp_commit() { asm volatile("cp.async.commit_group;"); }
__device__ __forceinline__ void cp_wait1() { asm volatile("cp.async.wait_group 1;"); }
__device__ __forceinline__ void cp_wait0() { asm volatile("cp.async.wait_group 0;"); }

// ============================================================
// Kernel 0: one-time bf16 conversion of weights + ln params
// ============================================================
__global__ void setup_kernel(
    const float* __restrict__ Wv, const float* __restrict__ Wk, const float* __restrict__ Wq,
    const float* __restrict__ Wo, const float* __restrict__ Wm1, const float* __restrict__ Wm2,
    const float* __restrict__ lng, const float* __restrict__ lnb)
{
    const int idx = blockIdx.x * blockDim.x + threadIdx.x;
    const int stride = gridDim.x * blockDim.x;
    for (int i = idx; i < 6 * 4096; i += stride) {
        const int m = i >> 12, r = i & 4095;
        const float* src = (m == 0) ? Wv : (m == 1) ? Wk : (m == 2) ? Wq
                         : (m == 3) ? Wo : (m == 4) ? Wm1 : Wm2;
        g_wb[i] = __float2bfloat16(src[r]);
    }
    for (int i = idx; i < SLAB_; i += stride) {
        g_lng[i] = __float2bfloat16(lng[i]);
        g_lnb[i] = __float2bfloat16(lnb[i]);
    }
}

// ============================================================
// Kernel 1: LayerNorm statistics per (b,e) slab (512 threads)
// ============================================================
__global__ void __launch_bounds__(512) ln_stats_kernel(const float* __restrict__ x) {
    const int be = blockIdx.x;
    const float4* p = (const float4*)(x + (size_t)be * SLAB_);
    float s = 0.f, s2 = 0.f;
    for (int i = threadIdx.x; i < SLAB_ / 4; i += 512) {
        float4 v = p[i];
        s  += v.x + v.y + v.z + v.w;
        s2 += v.x * v.x + v.y * v.y + v.z * v.z + v.w * v.w;
    }
    for (int o = 16; o; o >>= 1) {
        s  += __shfl_down_sync(0xffffffffu, s,  o);
        s2 += __shfl_down_sync(0xffffffffu, s2, o);
    }
    __shared__ float shs[16], shq[16];
    const int w = threadIdx.x >> 5, l = threadIdx.x & 31;
    if (l == 0) { shs[w] = s; shq[w] = s2; }
    __syncthreads();
    if (threadIdx.x == 0) {
        float S = 0.f, Q = 0.f;
        for (int i = 0; i < 16; i++) { S += shs[i]; Q += shq[i]; }
        const float mu  = S * (1.f / (float)SLAB_);
        const float var = Q * (1.f / (float)SLAB_) - mu * mu;
        g_mu[be] = mu;
        g_rs[be] = rsqrtf(var + 1e-5f);
    }
}

// ============================================================
// Kernel 2: fused LN + v/k/q conv. 256 threads; weights once
// per block; 8 hw-64 tiles processed in a loop.
// ============================================================
__global__ void __launch_bounds__(256) vkq_kernel(
    const float* __restrict__ x,
    bf16* __restrict__ ov, bf16* __restrict__ ok, bf16* __restrict__ oq)
{
    extern __shared__ bf16 smb[];
    bf16* Ws = smb;                // [3][64 o][SB_]
    bf16* Xs = smb + 3 * 64 * SB_; // [64 c][SB_] (64 hw cols)
    const int be = blockIdx.y, tid = threadIdx.x;
    const int wid = tid >> 5, lane = tid & 31;
    const int g = lane >> 2, tg = lane & 3;
    const int ob = (wid & 3) * 16;     // out-row tile
    const int nh0 = (wid >> 2) * 32;   // hw half (32 cols)

    const uint32 ws0 = cvta_smem(Ws);
    const uint32 xs0 = cvta_smem(Xs);

    for (int it = tid; it < 1536; it += 256) {
        const int m = it >> 9, rem = it & 511, o = rem >> 3, s8 = (rem & 7) << 3;
        cp16(ws0 + ((m * 64 * SB_ + o * SB_ + s8) << 1), &g_wb[m * 4096 + o * 64 + s8]);
    }
    cp_commit();

    const float mu = g_mu[be], rs = g_rs[be];
    const int bb = be / E_, ee = be % E_;
    const int rowA = ob + (lane & 15);
    const int colA = (lane >> 4) << 3;
    const int krow = lane & 15;
    const int hwadd = (lane >> 4) << 3;

    for (int t = 0; t < 8; t++) {
        const int hw0 = blockIdx.x * 512 + t * 64;
        if (t) __syncthreads();

        const float* xb = x + (size_t)be * SLAB_ + hw0;
        for (int rep = 0; rep < 8; rep++) {
            const int c = wid * 8 + rep;
            const int hw = 2 * lane;
            const float2 xv = *(const float2*)(xb + c * HW_ + hw);
            const bf162 gg = *(const bf162*)&g_lng[c * HW_ + hw0 + hw];
            const bf162 bb2 = *(const bf162*)&g_lnb[c * HW_ + hw0 + hw];
            const float2 gf = __bfloat1622float2(gg);
            const float2 bf = __bfloat1622float2(bb2);
            const float v0 = (xv.x - mu) * rs * gf.x + bf.x;
            const float v1 = (xv.y - mu) * rs * gf.y + bf.y;
            *(bf162*)&Xs[c * SB_ + hw] = __floats2bfloat162_rn(v0, v1);
        }
        if (t == 0) cp_wait0();
        __syncthreads();

        float acc[3][4][4];
#pragma unroll
        for (int m = 0; m < 3; m++)
#pragma unroll
            for (int nt = 0; nt < 4; nt++)
#pragma unroll
                for (int r = 0; r < 4; r++) acc[m][nt][r] = 0.f;

#pragma unroll
        for (int ks = 0; ks < 4; ks++) {
            const int kc = 16 * ks;
            uint32 b0[4], b1[4];
#pragma unroll
            for (int p = 0; p < 2; p++)
                ldsm4t(b0[2 * p], b1[2 * p], b0[2 * p + 1], b1[2 * p + 1],
                       xs0 + (((kc + krow) * SB_ + nh0 + 16 * p + hwadd) << 1));
#pragma unroll
            for (int m = 0; m < 3; m++) {
                uint32 a0, a1, a2, a3;
                ldsm4(a0, a1, a2, a3, ws0 + ((m * 64 * SB_ + rowA * SB_ + kc + colA) << 1));
#pragma unroll
                for (int nt = 0; nt < 4; nt++) mma16(acc[m][nt], a0, a1, a2, a3, b0[nt], b1[nt]);
            }
        }

        bf16* outs[3] = {ov, ok, oq};
#pragma unroll
        for (int m = 0; m < 3; m++) {
            bf16* dst = outs[m];
#pragma unroll
            for (int nt = 0; nt < 4; nt++) {
                const int hw = hw0 + nh0 + 8 * nt + 2 * tg;
                const int o0 = ob + g, o1 = ob + g + 8;
                *(bf162*)&dst[((size_t)(bb * C_ + o0) * E_ + ee) * HW_ + hw] =
                    __floats2bfloat162_rn(acc[m][nt][0], acc[m][nt][1]);
                *(bf162*)&dst[((size_t)(bb * C_ + o1) * E_ + ee) * HW_ + hw] =
                    __floats2bfloat162_rn(acc[m][nt][2], acc[m][nt][3]);
            }
        }
    }
}

// ============================================================
// Kernel 3: gram partials, z=4 split + FUSED softmax in the
// last-finishing block per (b,nh) (deterministic z-order sum).
// ============================================================
__global__ void __launch_bounds__(256) gram_kernel(
    const bf16* __restrict__ k, const bf16* __restrict__ q,
    float* __restrict__ part, float* __restrict__ wts)
{
    extern __shared__ bf16 smg[];
    bf16* Ks = smg;                 // [2 buf][64 i][SD_]
    bf16* Qs = smg + 2 * 64 * SD_;
    const int nh = blockIdx.x, b = blockIdx.y, z = blockIdx.z;
    const int tid = threadIdx.x;
    const int wid = tid >> 5, lane = tid & 31;
    const int g = lane >> 2, tg = lane & 3;
    const int wm = wid & 3, wn = wid >> 2;
    const int ib = wm * 16;
    const int jb = wn * 32;
    const int bc = b * C_ + nh;
    const bf16* kb = k + (size_t)bc * E_ * HW_;
    const bf16* qb = q + (size_t)bc * E_ * HW_;
    const int hwz = z * 512;

    for (int idx = tid; idx < 4 * 14 * 16; idx += 256) {
        const int a = idx / 224, rem = idx % 224, e = 50 + rem / 16, h8 = (rem % 16) << 3;
        bf16* base = (a & 1) ? Qs : Ks;
        *(uint4*)&base[(a >> 1) * 64 * SD_ + e * SD_ + h8] = make_uint4(0u, 0u, 0u, 0u);
    }

    const uint32 ks0 = cvta_smem(Ks);
    const uint32 qs0 = cvta_smem(Qs);

#pragma unroll
    for (int pre = 0; pre < 2; pre++) {
        for (int p = tid; p < 1600; p += 256) {
            const int arr = p / 800, rem = p % 800, e = rem >> 4, h8 = (rem & 15) << 3;
            const bf16* src = (arr ? qb : kb) + e * HW_ + hwz + pre * 128 + h8;
            const uint32 dst = (arr ? qs0 : ks0) + ((pre * 64 * SD_ + e * SD_ + h8) << 1);
            cp16(dst, src);
        }
        cp_commit();
    }

    const int rowA = ib + (lane & 15);
    const int colA = (lane >> 4) << 3;
    const int rowBb = lane & 7;
    const int colB = lane & 8;
    const int rowP = (lane >> 4) << 3;

    float acc[4][4];
#pragma unroll
    for (int nt = 0; nt < 4; nt++)
#pragma unroll
        for (int r = 0; r < 4; r++) acc[nt][r] = 0.f;

    for (int ch = 0; ch < 4; ch++) {
        const int buf = ch & 1;
        if (ch >= 3) cp_wait0(); else cp_wait1();
        __syncthreads();

        const uint32 kbase = ks0 + ((buf * 64 * SD_) << 1);
        const uint32 qbase = qs0 + ((buf * 64 * SD_) << 1);
#pragma unroll
        for (int ks = 0; ks < 8; ks++) {
            const int kc = 16 * ks;
            uint32 a0, a1, a2, a3;
            ldsm4(a0, a1, a2, a3, kbase + ((rowA * SD_ + kc + colA) << 1));
            uint32 bb0[4], bb1[4];
#pragma unroll
            for (int np = 0; np < 2; np++)
                ldsm4(bb0[2 * np], bb1[2 * np], bb0[2 * np + 1], bb1[2 * np + 1],
                      qbase + (((jb + 16 * np + rowP + rowBb) * SD_ + kc + colB) << 1));
#pragma unroll
            for (int nt = 0; nt < 4; nt++)
                mma16(acc[nt], a0, a1, a2, a3, bb0[nt], bb1[nt]);
        }
        __syncthreads();

        if (ch + 2 < 4) {
            const int nxt = ch + 2;
            for (int p = tid; p < 1600; p += 256) {
                const int arr = p / 800, rem = p % 800, e = rem >> 4, h8 = (rem & 15) << 3;
                const bf16* src = (arr ? qb : kb) + e * HW_ + hwz + nxt * 128 + h8;
                const uint32 dst = (arr ? qs0 : ks0) + ((buf * 64 * SD_ + e * SD_ + h8) << 1);
                cp16(dst, src);
            }
            cp_commit();
        }
    }

    float* pd = part + (((size_t)bc * 4 + z) * (64 * 64));
#pragma unroll
    for (int nt = 0; nt < 4; nt++) {
        const int j = jb + 8 * nt + 2 * tg;
        *(float2*)&pd[(ib + g) * 64 + j]     = make_float2(acc[nt][0], acc[nt][1]);
        *(float2*)&pd[(ib + g + 8) * 64 + j] = make_float2(acc[nt][2], acc[nt][3]);
    }

    // ---- last-block-done: reduce 4 partials + softmax + w' = p - 1/E ----
    __shared__ unsigned s_old;
    __syncthreads();             // all partial stores issued
    if (tid == 0) {
        __threadfence();         // make this block's partials visible
        s_old = atomicAdd(&g_cnt[bc], 1u);
    }
    __syncthreads();
    if (s_old == 3u) {
        if (tid == 0) g_cnt[bc] = 0u;   // self-reset for next launch/replay
        __threadfence();                // acquire: see other blocks' partials
        if (tid < E_) {
            const int j = tid;
            const float* pp = part + (size_t)bc * 4 * (64 * 64);
            const float scale = 0.02209708691207961f;  // 1/sqrt(2048)
            float col[E_];
            float m = -1e30f;
#pragma unroll 10
            for (int i = 0; i < E_; i++) {
                float s = pp[i * 64 + j] + pp[4096 + i * 64 + j]
                        + pp[8192 + i * 64 + j] + pp[12288 + i * 64 + j];
                col[i] = s * scale;
                m = fmaxf(m, col[i]);
            }
            float s = 0.f;
#pragma unroll 10
            for (int i = 0; i < E_; i++) { col[i] = expf(col[i] - m); s += col[i]; }
            const float inv = 1.f / s;
            float* wd = wts + (size_t)bc * E_ * E_;
#pragma unroll 10
            for (int i = 0; i < E_; i++) wd[i * E_ + j] = col[i] * inv - 0.02f;
        }
    }
}

// ============================================================
// Kernel 4: ensemble mixing, M = I + w' (proven R13 version).
// ============================================================
__global__ void __launch_bounds__(128) mixing_kernel(
    const bf16* __restrict__ v, const float* __restrict__ w,
    bf16* __restrict__ tout)
{
    extern __shared__ bf16 smx[];
    bf16* Ms = smx;                // [64 j][SB_] cols i
    bf16* Vs = smx + 64 * SB_;     // [2 buf][64 i][SB_] cols hw
    const int nh = blockIdx.x, b = blockIdx.y, z = blockIdx.z;
    const int tid = threadIdx.x, wid = tid >> 5, lane = tid & 31;
    const int g = lane >> 2, tg = lane & 3;
    const int ob = wid * 16;
    const int bc = b * C_ + nh;

    for (int idx = tid; idx < 64 * 8; idx += 128)
        *(uint4*)&Ms[(idx >> 3) * SB_ + ((idx & 7) << 3)] = make_uint4(0u, 0u, 0u, 0u);
    for (int idx = tid; idx < 2 * 14 * 8; idx += 128) {
        const int bfi = idx / 112, rem = idx % 112;
        *(uint4*)&Vs[bfi * 64 * SB_ + (50 + (rem >> 3)) * SB_ + ((rem & 7) << 3)] =
            make_uint4(0u, 0u, 0u, 0u);
    }
    __syncthreads();
    const float* wsrc = w + (size_t)bc * E_ * E_;
    for (int idx = tid; idx < E_ * E_; idx += 128) {
        const int i = idx / E_, j = idx - i * E_;
        const float val = wsrc[idx] + ((i == j) ? 1.f : 0.f);
        Ms[j * SB_ + i] = __float2bfloat16(val);
    }

    const bf16* vb = v + (size_t)bc * E_ * HW_;
    const uint32 ms0 = cvta_smem(Ms);
    const uint32 vs0 = cvta_smem(Vs);

#pragma unroll
    for (int pre = 0; pre < 2; pre++) {
        for (int p = tid; p < 400; p += 128) {
            const int e = p >> 3, h8 = (p & 7) << 3;
            cp16(vs0 + ((pre * 64 * SB_ + e * SB_ + h8) << 1),
                 vb + e * HW_ + z * 512 + pre * 64 + h8);
        }
        cp_commit();
    }

    const int rowA = ob + (lane & 15);
    const int colA = (lane >> 4) << 3;
    const int krow = lane & 15;
    const int hwadd = (lane >> 4) << 3;

    for (int t = 0; t < 8; t++) {
        const int buf = t & 1;
        const int hw0 = z * 512 + t * 64;
        if (t >= 7) cp_wait0(); else cp_wait1();
        __syncthreads();

        const uint32 vbase = vs0 + ((buf * 64 * SB_) << 1);
        float acc[8][4];
#pragma unroll
        for (int nt = 0; nt < 8; nt++)
#pragma unroll
            for (int r = 0; r < 4; r++) acc[nt][r] = 0.f;

#pragma unroll
        for (int ks = 0; ks < 4; ks++) {
            const int kc = 16 * ks;
            uint32 a0, a1, a2, a3;
            ldsm4(a0, a1, a2, a3, ms0 + ((rowA * SB_ + kc + colA) << 1));
            uint32 b0[8], b1[8];
#pragma unroll
            for (int p = 0; p < 4; p++)
                ldsm4t(b0[2 * p], b1[2 * p], b0[2 * p + 1], b1[2 * p + 1],
                       vbase + (((kc + krow) * SB_ + 16 * p + hwadd) << 1));
#pragma unroll
            for (int nt = 0; nt < 8; nt++)
                mma16(acc[nt], a0, a1, a2, a3, b0[nt], b1[nt]);
        }
        __syncthreads();

        if (t + 2 < 8) {
            for (int p = tid; p < 400; p += 128) {
                const int e = p >> 3, h8 = (p & 7) << 3;
                cp16(vs0 + ((buf * 64 * SB_ + e * SB_ + h8) << 1),
                     vb + e * HW_ + z * 512 + (t + 2) * 64 + h8);
            }
            cp_commit();
        }

        const int j0 = ob + g, j1 = ob + g + 8;
#pragma unroll
        for (int nt = 0; nt < 8; nt++) {
            const int hw = 8 * nt + 2 * tg;
            if (j0 < E_)
                *(bf162*)&tout[((size_t)(b * E_ + j0) * C_ + nh) * HW_ + hw0 + hw] =
                    __floats2bfloat162_rn(acc[nt][0], acc[nt][1]);
            if (j1 < E_)
                *(bf162*)&tout[((size_t)(b * E_ + j1) * C_ + nh) * HW_ + hw0 + hw] =
                    __floats2bfloat162_rn(acc[nt][2], acc[nt][3]);
        }
    }
}

// ============================================================
// Kernel 5: fused tail. 256 threads; weights once per block;
// 8 hw-64 tiles per block with double-buffered T prefetch.
// ============================================================
__global__ void __launch_bounds__(256) tail_kernel(
    const bf16* __restrict__ T, const float* __restrict__ x,
    const float* __restrict__ bm1, const float* __restrict__ bm2,
    float* __restrict__ out)
{
    extern __shared__ bf16 smt[];
    bf16* Ws = smt;                // [3][64 o][SB_]
    bf16* D0 = smt + 3 * 64 * SB_; // [2 buf][64 c][SB_]
    const int be = blockIdx.y, tid = threadIdx.x;
    const int wid = tid >> 5, lane = tid & 31;
    const int g = lane >> 2, tg = lane & 3;
    const int ob = (wid & 3) * 16;
    const int nh0 = (wid >> 2) * 32;

    const uint32 ws0 = cvta_smem(Ws);
    const uint32 d0s = cvta_smem(D0);

    for (int it = tid; it < 1536; it += 256) {
        const int m = it >> 9, rem = it & 511, o = rem >> 3, s8 = (rem & 7) << 3;
        cp16(ws0 + ((m * 64 * SB_ + o * SB_ + s8) << 1), &g_wb[(3 + m) * 4096 + o * 64 + s8]);
    }
    const bf16* tbase = T + (size_t)be * SLAB_ + blockIdx.x * 512;
    for (int p = tid; p < 512; p += 256) {
        const int c = p >> 3, h8 = (p & 7) << 3;
        cp16(d0s + ((c * SB_ + h8) << 1), tbase + c * HW_ + h8);
    }
    cp_commit();

    const float* xbase = x + (size_t)be * SLAB_ + blockIdx.x * 512;
    const int rowA = ob + (lane & 15);
    const int colA = (lane >> 4) << 3;
    const int krow = lane & 15;
    const int hwadd = (lane >> 4) << 3;

    for (int t = 0; t < 8; t++) {
        const int buf = t & 1;
        const int hwt = t * 64;
        const uint32 ds0 = d0s + ((buf * 64 * SB_) << 1);
        bf16* Ds = D0 + buf * 64 * SB_;

        if (t < 7) {
            for (int p = tid; p < 512; p += 256) {
                const int c = p >> 3, h8 = (p & 7) << 3;
                cp16(d0s + ((((1 - buf) * 64 * SB_) + c * SB_ + h8) << 1),
                     tbase + c * HW_ + hwt + 64 + h8);
            }
            cp_commit();
            cp_wait1();
        } else {
            cp_wait0();
        }

        float acc1[4][4];
#pragma unroll
        for (int nt = 0; nt < 4; nt++) {
            const int hw = hwt + nh0 + 8 * nt + 2 * tg;
            const float2 r0 = *(const float2*)(xbase + (size_t)(ob + g) * HW_ + hw);
            const float2 r1 = *(const float2*)(xbase + (size_t)(ob + g + 8) * HW_ + hw);
            acc1[nt][0] = r0.x; acc1[nt][1] = r0.y; acc1[nt][2] = r1.x; acc1[nt][3] = r1.y;
        }
        __syncthreads();

#pragma unroll
        for (int ks = 0; ks < 4; ks++) {
            const int kc = 16 * ks;
            uint32 a0, a1, a2, a3;
            ldsm4(a0, a1, a2, a3, ws0 + ((rowA * SB_ + kc + colA) << 1));
            uint32 b0[4], b1[4];
#pragma unroll
            for (int p = 0; p < 2; p++)
                ldsm4t(b0[2 * p], b1[2 * p], b0[2 * p + 1], b1[2 * p + 1],
                       ds0 + (((kc + krow) * SB_ + nh0 + 16 * p + hwadd) << 1));
#pragma unroll
            for (int nt = 0; nt < 4; nt++)
                mma16(acc1[nt], a0, a1, a2, a3, b0[nt], b1[nt]);
        }
        __syncthreads();

#pragma unroll
        for (int nt = 0; nt < 4; nt++) {
            const int hw = nh0 + 8 * nt + 2 * tg;
            *(bf162*)&Ds[(ob + g) * SB_ + hw]     = __floats2bfloat162_rn(acc1[nt][0], acc1[nt][1]);
            *(bf162*)&Ds[(ob + g + 8) * SB_ + hw] = __floats2bfloat162_rn(acc1[nt][2], acc1[nt][3]);
        }
        __syncthreads();

        float acc2[4][4];
        {
            const float bv0 = bm1[ob + g], bv1 = bm1[ob + g + 8];
#pragma unroll
            for (int nt = 0; nt < 4; nt++) {
                acc2[nt][0] = bv0; acc2[nt][1] = bv0; acc2[nt][2] = bv1; acc2[nt][3] = bv1;
            }
        }
#pragma unroll
        for (int ks = 0; ks < 4; ks++) {
            const int kc = 16 * ks;
            uint32 a0, a1, a2, a3;
            ldsm4(a0, a1, a2, a3, ws0 + ((64 * SB_ + rowA * SB_ + kc + colA) << 1));
            uint32 b0[4], b1[4];
#pragma unroll
            for (int p = 0; p < 2; p++)
                ldsm4t(b0[2 * p], b1[2 * p], b0[2 * p + 1], b1[2 * p + 1],
                       ds0 + (((kc + krow) * SB_ + nh0 + 16 * p + hwadd) << 1));
#pragma unroll
            for (int nt = 0; nt < 4; nt++)
                mma16(acc2[nt], a0, a1, a2, a3, b0[nt], b1[nt]);
        }
#pragma unroll
        for (int nt = 0; nt < 4; nt++)
#pragma unroll
            for (int r = 0; r < 4; r++) {
                const float v = acc2[nt][r];
                acc2[nt][r] = 0.5f * v * (1.f + erff(v * 0.7071067811865475f));
            }
        __syncthreads();

#pragma unroll
        for (int nt = 0; nt < 4; nt++) {
            const int hw = nh0 + 8 * nt + 2 * tg;
            *(bf162*)&Ds[(ob + g) * SB_ + hw]     = __floats2bfloat162_rn(acc2[nt][0], acc2[nt][1]);
            *(bf162*)&Ds[(ob + g + 8) * SB_ + hw] = __floats2bfloat162_rn(acc2[nt][2], acc2[nt][3]);
        }
        __syncthreads();

        {
            const float bv0 = bm2[ob + g], bv1 = bm2[ob + g + 8];
#pragma unroll
            for (int nt = 0; nt < 4; nt++) {
                acc2[nt][0] = bv0; acc2[nt][1] = bv0; acc2[nt][2] = bv1; acc2[nt][3] = bv1;
            }
        }
#pragma unroll
        for (int ks = 0; ks < 4; ks++) {
            const int kc = 16 * ks;
            uint32 a0, a1, a2, a3;
            ldsm4(a0, a1, a2, a3, ws0 + ((2 * 64 * SB_ + rowA * SB_ + kc + colA) << 1));
            uint32 b0[4], b1[4];
#pragma unroll
            for (int p = 0; p < 2; p++)
                ldsm4t(b0[2 * p], b1[2 * p], b0[2 * p + 1], b1[2 * p + 1],
                       ds0 + (((kc + krow) * SB_ + nh0 + 16 * p + hwadd) << 1));
#pragma unroll
            for (int nt = 0; nt < 4; nt++)
                mma16(acc2[nt], a0, a1, a2, a3, b0[nt], b1[nt]);
        }

        float* dst = out + (size_t)be * SLAB_ + blockIdx.x * 512;
#pragma unroll
        for (int nt = 0; nt < 4; nt++) {
            const int hw = hwt + nh0 + 8 * nt + 2 * tg;
            *(float2*)(dst + (size_t)(ob + g) * HW_ + hw) =
                make_float2(acc1[nt][0] + acc2[nt][0], acc1[nt][1] + acc2[nt][1]);
            *(float2*)(dst + (size_t)(ob + g + 8) * HW_ + hw) =
                make_float2(acc1[nt][2] + acc2[nt][2], acc1[nt][3] + acc2[nt][3]);
        }
        __syncthreads();
    }
}

// ============================================================
// Launch
// ============================================================
extern "C" void kernel_launch(void* const* d_in, const int* in_sizes, int n_in,
                              void* d_out, int out_size)
{
    const float* x    = (const float*)d_in[0];
    const float* lng  = (const float*)d_in[1];
    const float* lnb  = (const float*)d_in[2];
    const float* W_v  = (const float*)d_in[3];
    const float* W_k  = (const float*)d_in[4];
    const float* W_q  = (const float*)d_in[5];
    const float* W_o  = (const float*)d_in[6];
    const float* W_m1 = (const float*)d_in[7];
    const float* b_m1 = (const float*)d_in[8];
    const float* W_m2 = (const float*)d_in[9];
    const float* b_m2 = (const float*)d_in[10];
    float* out = (float*)d_out;

    bf16 *pv, *pk, *pq, *pt;
    float *pw, *pp;
    cudaGetSymbolAddress((void**)&pv, g_v);
    cudaGetSymbolAddress((void**)&pk, g_k);
    cudaGetSymbolAddress((void**)&pq, g_q);
    cudaGetSymbolAddress((void**)&pt, g_t);
    cudaGetSymbolAddress((void**)&pw, g_wts);
    cudaGetSymbolAddress((void**)&pp, g_part);

    const int smem_vkq  = (3 * 64 * SB_ + 64 * SB_) * 2;      // 36864
    const int smem_gram = (4 * 64 * SD_) * 2;                 // 69632
    const int smem_mix  = (3 * 64 * SB_) * 2;                 // 27648
    const int smem_tail = (3 * 64 * SB_ + 2 * 64 * SB_) * 2;  // 46080
    cudaFuncSetAttribute(vkq_kernel,    cudaFuncAttributeMaxDynamicSharedMemorySize, smem_vkq);
    cudaFuncSetAttribute(gram_kernel,   cudaFuncAttributeMaxDynamicSharedMemorySize, smem_gram);
    cudaFuncSetAttribute(mixing_kernel, cudaFuncAttributeMaxDynamicSharedMemorySize, smem_mix);
    cudaFuncSetAttribute(tail_kernel,   cudaFuncAttributeMaxDynamicSharedMemorySize, smem_tail);

    setup_kernel<<<128, 256>>>(W_v, W_k, W_q, W_o, W_m1, W_m2, lng, lnb);

    ln_stats_kernel<<<BE_, 512>>>(x);

    vkq_kernel<<<dim3(HW_ / 512, BE_), 256, smem_vkq>>>(x, pv, pk, pq);

    gram_kernel<<<dim3(C_, B_, 4), 256, smem_gram>>>(pk, pq, pp, pw);

    mixing_kernel<<<dim3(C_, B_, 4), 128, smem_mix>>>(pv, pw, pt);

    tail_kernel<<<dim3(HW_ / 512, BE_), 256, smem_tail>>>(pt, x, b_m1, b_m2, out);
}

// round 16
// speedup vs baseline: 1.0660x; 1.0660x over previous
#include <cuda_runtime.h>
#include <cuda_bf16.h>
#include <math.h>

#define B_    4
#define E_    50
#define C_    64
#define HW_   2048
#define BE_   200
#define SLAB_ 131072      // C_*HW_
#define NTOT_ 26214400    // BE_*SLAB_
#define SB_   72          // bf16 smem row stride, 64 cols (LDSM conflict-free)
#define SD_   136         // bf16 smem row stride, 128 cols (LDSM conflict-free)

typedef unsigned int uint32;
typedef __nv_bfloat16 bf16;
typedef __nv_bfloat162 bf162;

// ---- scratch (static device globals; no allocation) ----
__device__ bf16 g_v[NTOT_];   // [b][c][e][hw]
__device__ bf16 g_k[NTOT_];   // [b][c][e][hw]
__device__ bf16 g_q[NTOT_];   // [b][c][e][hw]
__device__ bf16 g_t[NTOT_];   // [b][e][c][hw]
__device__ float g_wts[B_ * C_ * E_ * E_];       // w' = softmax - 1/E
__device__ float g_part[B_ * C_ * 4 * 64 * 64];  // gram partials per z (stride 64)
__device__ float g_mu[BE_];
__device__ float g_rs[BE_];
__device__ bf16 g_wb[6 * 4096];   // bf16 weights: Wv,Wk,Wq,Wo,Wm1,Wm2 [o][c]
__device__ bf16 g_lng[SLAB_];
__device__ bf16 g_lnb[SLAB_];

// m16n8k16 bf16 mma, fp32 accumulate
__device__ __forceinline__ void mma16(float d[4], uint32 a0, uint32 a1, uint32 a2, uint32 a3,
                                      uint32 b0, uint32 b1) {
    asm volatile(
        "mma.sync.aligned.m16n8k16.row.col.f32.bf16.bf16.f32 "
        "{%0,%1,%2,%3}, {%4,%5,%6,%7}, {%8,%9}, {%0,%1,%2,%3};"
        : "+f"(d[0]), "+f"(d[1]), "+f"(d[2]), "+f"(d[3])
        : "r"(a0), "r"(a1), "r"(a2), "r"(a3), "r"(b0), "r"(b1));
}

__device__ __forceinline__ uint32 cvta_smem(const void* p) {
    return (uint32)__cvta_generic_to_shared(p);
}
__device__ __forceinline__ void ldsm4(uint32& r0, uint32& r1, uint32& r2, uint32& r3, uint32 a) {
    asm volatile("ldmatrix.sync.aligned.m8n8.x4.shared.b16 {%0,%1,%2,%3}, [%4];"
                 : "=r"(r0), "=r"(r1), "=r"(r2), "=r"(r3) : "r"(a));
}
__device__ __forceinline__ void ldsm4t(uint32& r0, uint32& r1, uint32& r2, uint32& r3, uint32 a) {
    asm volatile("ldmatrix.sync.aligned.m8n8.x4.trans.shared.b16 {%0,%1,%2,%3}, [%4];"
                 : "=r"(r0), "=r"(r1), "=r"(r2), "=r"(r3) : "r"(a));
}
__device__ __forceinline__ void cp16(uint32 dst, const void* src) {
    asm volatile("cp.async.cg.shared.global [%0], [%1], 16;" :: "r"(dst), "l"(src));
}
__device__ __forceinline__ void cp_commit() { asm volatile("cp.async.commit_group;"); }
__device__ __forceinline__ void cp_wait1() { asm volatile("cp.async.wait_group 1;"); }
__device__ __forceinline__ void cp_wait0() { asm volatile("cp.async.wait_group 0;"); }

// ============================================================
// Kernel 0: one-time bf16 conversion of weights + ln params
// ============================================================
__global__ void setup_kernel(
    const float* __restrict__ Wv, const float* __restrict__ Wk, const float* __restrict__ Wq,
    const float* __restrict__ Wo, const float* __restrict__ Wm1, const float* __restrict__ Wm2,
    const float* __restrict__ lng, const float* __restrict__ lnb)
{
    const int idx = blockIdx.x * blockDim.x + threadIdx.x;
    const int stride = gridDim.x * blockDim.x;
    for (int i = idx; i < 6 * 4096; i += stride) {
        const int m = i >> 12, r = i & 4095;
        const float* src = (m == 0) ? Wv : (m == 1) ? Wk : (m == 2) ? Wq
                         : (m == 3) ? Wo : (m == 4) ? Wm1 : Wm2;
        g_wb[i] = __float2bfloat16(src[r]);
    }
    for (int i = idx; i < SLAB_; i += stride) {
        g_lng[i] = __float2bfloat16(lng[i]);
        g_lnb[i] = __float2bfloat16(lnb[i]);
    }
}

// ============================================================
// Kernel 1: LayerNorm statistics per (b,e) slab (512 threads)
// ============================================================
__global__ void __launch_bounds__(512) ln_stats_kernel(const float* __restrict__ x) {
    const int be = blockIdx.x;
    const float4* p = (const float4*)(x + (size_t)be * SLAB_);
    float s = 0.f, s2 = 0.f;
    for (int i = threadIdx.x; i < SLAB_ / 4; i += 512) {
        float4 v = p[i];
        s  += v.x + v.y + v.z + v.w;
        s2 += v.x * v.x + v.y * v.y + v.z * v.z + v.w * v.w;
    }
    for (int o = 16; o; o >>= 1) {
        s  += __shfl_down_sync(0xffffffffu, s,  o);
        s2 += __shfl_down_sync(0xffffffffu, s2, o);
    }
    __shared__ float shs[16], shq[16];
    const int w = threadIdx.x >> 5, l = threadIdx.x & 31;
    if (l == 0) { shs[w] = s; shq[w] = s2; }
    __syncthreads();
    if (threadIdx.x == 0) {
        float S = 0.f, Q = 0.f;
        for (int i = 0; i < 16; i++) { S += shs[i]; Q += shq[i]; }
        const float mu  = S * (1.f / (float)SLAB_);
        const float var = Q * (1.f / (float)SLAB_) - mu * mu;
        g_mu[be] = mu;
        g_rs[be] = rsqrtf(var + 1e-5f);
    }
}

// ============================================================
// Kernel 2: fused LN + v/k/q conv. 256 threads; weights loaded
// ONCE per block, then 4 hw-64 tiles processed in a loop.
// Warp = (out-tile 16) x (hw-half 32); acc[3][4][4] = 48 regs.
// ============================================================
__global__ void __launch_bounds__(256) vkq_kernel(
    const float* __restrict__ x,
    bf16* __restrict__ ov, bf16* __restrict__ ok, bf16* __restrict__ oq)
{
    extern __shared__ bf16 smb[];
    bf16* Ws = smb;                // [3][64 o][SB_]
    bf16* Xs = smb + 3 * 64 * SB_; // [64 c][SB_] (64 hw cols)
    const int be = blockIdx.y, tid = threadIdx.x;
    const int wid = tid >> 5, lane = tid & 31;
    const int g = lane >> 2, tg = lane & 3;
    const int ob = (wid & 3) * 16;     // out-row tile
    const int nh0 = (wid >> 2) * 32;   // hw half (32 cols)

    const uint32 ws0 = cvta_smem(Ws);
    const uint32 xs0 = cvta_smem(Xs);

    // weights via cp.async (bf16), once per block
    for (int it = tid; it < 1536; it += 256) {
        const int m = it >> 9, rem = it & 511, o = rem >> 3, s8 = (rem & 7) << 3;
        cp16(ws0 + ((m * 64 * SB_ + o * SB_ + s8) << 1), &g_wb[m * 4096 + o * 64 + s8]);
    }
    cp_commit();

    const float mu = g_mu[be], rs = g_rs[be];
    const int bb = be / E_, ee = be % E_;
    const int rowA = ob + (lane & 15);
    const int colA = (lane >> 4) << 3;
    const int krow = lane & 15;
    const int hwadd = (lane >> 4) << 3;

    for (int t = 0; t < 4; t++) {
        const int hw0 = blockIdx.x * 256 + t * 64;
        if (t) __syncthreads();   // previous tile's mma reads of Xs done

        // x tile: LN -> Xs[c][hw], 64c x 64hw
        const float* xb = x + (size_t)be * SLAB_ + hw0;
        for (int rep = 0; rep < 8; rep++) {
            const int c = wid * 8 + rep;
            const int hw = 2 * lane;
            const float2 xv = *(const float2*)(xb + c * HW_ + hw);
            const bf162 gg = *(const bf162*)&g_lng[c * HW_ + hw0 + hw];
            const bf162 bb2 = *(const bf162*)&g_lnb[c * HW_ + hw0 + hw];
            const float2 gf = __bfloat1622float2(gg);
            const float2 bf = __bfloat1622float2(bb2);
            const float v0 = (xv.x - mu) * rs * gf.x + bf.x;
            const float v1 = (xv.y - mu) * rs * gf.y + bf.y;
            *(bf162*)&Xs[c * SB_ + hw] = __floats2bfloat162_rn(v0, v1);
        }
        if (t == 0) cp_wait0();
        __syncthreads();

        float acc[3][4][4];
#pragma unroll
        for (int m = 0; m < 3; m++)
#pragma unroll
            for (int nt = 0; nt < 4; nt++)
#pragma unroll
                for (int r = 0; r < 4; r++) acc[m][nt][r] = 0.f;

#pragma unroll
        for (int ks = 0; ks < 4; ks++) {
            const int kc = 16 * ks;
            uint32 b0[4], b1[4];
#pragma unroll
            for (int p = 0; p < 2; p++)
                ldsm4t(b0[2 * p], b1[2 * p], b0[2 * p + 1], b1[2 * p + 1],
                       xs0 + (((kc + krow) * SB_ + nh0 + 16 * p + hwadd) << 1));
#pragma unroll
            for (int m = 0; m < 3; m++) {
                uint32 a0, a1, a2, a3;
                ldsm4(a0, a1, a2, a3, ws0 + ((m * 64 * SB_ + rowA * SB_ + kc + colA) << 1));
#pragma unroll
                for (int nt = 0; nt < 4; nt++) mma16(acc[m][nt], a0, a1, a2, a3, b0[nt], b1[nt]);
            }
        }

        bf16* outs[3] = {ov, ok, oq};
#pragma unroll
        for (int m = 0; m < 3; m++) {
            bf16* dst = outs[m];
#pragma unroll
            for (int nt = 0; nt < 4; nt++) {
                const int hw = hw0 + nh0 + 8 * nt + 2 * tg;
                const int o0 = ob + g, o1 = ob + g + 8;
                *(bf162*)&dst[((size_t)(bb * C_ + o0) * E_ + ee) * HW_ + hw] =
                    __floats2bfloat162_rn(acc[m][nt][0], acc[m][nt][1]);
                *(bf162*)&dst[((size_t)(bb * C_ + o1) * E_ + ee) * HW_ + hw] =
                    __floats2bfloat162_rn(acc[m][nt][2], acc[m][nt][3]);
            }
        }
    }
}

// ============================================================
// Kernel 3: gram partials, z=4 split (proven R10 version).
// ============================================================
__global__ void __launch_bounds__(256) gram_kernel(
    const bf16* __restrict__ k, const bf16* __restrict__ q,
    float* __restrict__ part)
{
    extern __shared__ bf16 smg[];
    bf16* Ks = smg;                 // [2 buf][64 i][SD_]
    bf16* Qs = smg + 2 * 64 * SD_;
    const int nh = blockIdx.x, b = blockIdx.y, z = blockIdx.z;
    const int tid = threadIdx.x;
    const int wid = tid >> 5, lane = tid & 31;
    const int g = lane >> 2, tg = lane & 3;
    const int wm = wid & 3, wn = wid >> 2;
    const int ib = wm * 16;
    const int jb = wn * 32;
    const bf16* kb = k + (size_t)(b * C_ + nh) * E_ * HW_;
    const bf16* qb = q + (size_t)(b * C_ + nh) * E_ * HW_;
    const int hwz = z * 512;

    for (int idx = tid; idx < 4 * 14 * 16; idx += 256) {
        const int a = idx / 224, rem = idx % 224, e = 50 + rem / 16, h8 = (rem % 16) << 3;
        bf16* base = (a & 1) ? Qs : Ks;
        *(uint4*)&base[(a >> 1) * 64 * SD_ + e * SD_ + h8] = make_uint4(0u, 0u, 0u, 0u);
    }

    const uint32 ks0 = cvta_smem(Ks);
    const uint32 qs0 = cvta_smem(Qs);

#pragma unroll
    for (int pre = 0; pre < 2; pre++) {
        for (int p = tid; p < 1600; p += 256) {
            const int arr = p / 800, rem = p % 800, e = rem >> 4, h8 = (rem & 15) << 3;
            const bf16* src = (arr ? qb : kb) + e * HW_ + hwz + pre * 128 + h8;
            const uint32 dst = (arr ? qs0 : ks0) + ((pre * 64 * SD_ + e * SD_ + h8) << 1);
            cp16(dst, src);
        }
        cp_commit();
    }

    const int rowA = ib + (lane & 15);
    const int colA = (lane >> 4) << 3;
    const int rowBb = lane & 7;
    const int colB = lane & 8;
    const int rowP = (lane >> 4) << 3;

    float acc[4][4];
#pragma unroll
    for (int nt = 0; nt < 4; nt++)
#pragma unroll
        for (int r = 0; r < 4; r++) acc[nt][r] = 0.f;

    for (int ch = 0; ch < 4; ch++) {
        const int buf = ch & 1;
        if (ch >= 3) cp_wait0(); else cp_wait1();
        __syncthreads();

        const uint32 kbase = ks0 + ((buf * 64 * SD_) << 1);
        const uint32 qbase = qs0 + ((buf * 64 * SD_) << 1);
#pragma unroll
        for (int ks = 0; ks < 8; ks++) {
            const int kc = 16 * ks;
            uint32 a0, a1, a2, a3;
            ldsm4(a0, a1, a2, a3, kbase + ((rowA * SD_ + kc + colA) << 1));
            uint32 bb0[4], bb1[4];
#pragma unroll
            for (int np = 0; np < 2; np++)
                ldsm4(bb0[2 * np], bb1[2 * np], bb0[2 * np + 1], bb1[2 * np + 1],
                      qbase + (((jb + 16 * np + rowP + rowBb) * SD_ + kc + colB) << 1));
#pragma unroll
            for (int nt = 0; nt < 4; nt++)
                mma16(acc[nt], a0, a1, a2, a3, bb0[nt], bb1[nt]);
        }
        __syncthreads();

        if (ch + 2 < 4) {
            const int nxt = ch + 2;
            for (int p = tid; p < 1600; p += 256) {
                const int arr = p / 800, rem = p % 800, e = rem >> 4, h8 = (rem & 15) << 3;
                const bf16* src = (arr ? qb : kb) + e * HW_ + hwz + nxt * 128 + h8;
                const uint32 dst = (arr ? qs0 : ks0) + ((buf * 64 * SD_ + e * SD_ + h8) << 1);
                cp16(dst, src);
            }
            cp_commit();
        }
    }

    float* pd = part + (((size_t)(b * C_ + nh) * 4 + z) * (64 * 64));
#pragma unroll
    for (int nt = 0; nt < 4; nt++) {
        const int j = jb + 8 * nt + 2 * tg;
        *(float2*)&pd[(ib + g) * 64 + j]     = make_float2(acc[nt][0], acc[nt][1]);
        *(float2*)&pd[(ib + g + 8) * 64 + j] = make_float2(acc[nt][2], acc[nt][3]);
    }
}

// ============================================================
// Kernel 3b: reduce partials + softmax over i; w' = p - 1/E.
// ============================================================
__global__ void __launch_bounds__(256) softmax_kernel(const float* __restrict__ part,
                                                      float* __restrict__ wts) {
    const int bc = blockIdx.x * 4 + (threadIdx.x >> 6);
    const int j = threadIdx.x & 63;
    if (j >= E_) return;
    const float* pp = part + (size_t)bc * 4 * (64 * 64);
    const float scale = 0.02209708691207961f;  // 1/sqrt(2048)
    float col[E_];
    float m = -1e30f;
#pragma unroll 10
    for (int i = 0; i < E_; i++) {
        float s = pp[i * 64 + j] + pp[4096 + i * 64 + j]
                + pp[8192 + i * 64 + j] + pp[12288 + i * 64 + j];
        col[i] = s * scale;
        m = fmaxf(m, col[i]);
    }
    float s = 0.f;
#pragma unroll 10
    for (int i = 0; i < E_; i++) { col[i] = expf(col[i] - m); s += col[i]; }
    const float inv = 1.f / s;
    float* wd = wts + (size_t)bc * E_ * E_;
#pragma unroll 10
    for (int i = 0; i < E_; i++) wd[i * E_ + j] = col[i] * inv - 0.02f;
}

// ============================================================
// Kernel 4: ensemble mixing, M = I + w' (proven R10 version).
// ============================================================
__global__ void __launch_bounds__(128) mixing_kernel(
    const bf16* __restrict__ v, const float* __restrict__ w,
    bf16* __restrict__ tout)
{
    extern __shared__ bf16 smx[];
    bf16* Ms = smx;                // [64 j][SB_] cols i
    bf16* Vs = smx + 64 * SB_;     // [2 buf][64 i][SB_] cols hw
    const int nh = blockIdx.x, b = blockIdx.y, z = blockIdx.z;
    const int tid = threadIdx.x, wid = tid >> 5, lane = tid & 31;
    const int g = lane >> 2, tg = lane & 3;
    const int ob = wid * 16;
    const int bc = b * C_ + nh;

    for (int idx = tid; idx < 64 * 8; idx += 128)
        *(uint4*)&Ms[(idx >> 3) * SB_ + ((idx & 7) << 3)] = make_uint4(0u, 0u, 0u, 0u);
    for (int idx = tid; idx < 2 * 14 * 8; idx += 128) {
        const int bfi = idx / 112, rem = idx % 112;
        *(uint4*)&Vs[bfi * 64 * SB_ + (50 + (rem >> 3)) * SB_ + ((rem & 7) << 3)] =
            make_uint4(0u, 0u, 0u, 0u);
    }
    __syncthreads();
    const float* wsrc = w + (size_t)bc * E_ * E_;
    for (int idx = tid; idx < E_ * E_; idx += 128) {
        const int i = idx / E_, j = idx - i * E_;
        const float val = wsrc[idx] + ((i == j) ? 1.f : 0.f);
        Ms[j * SB_ + i] = __float2bfloat16(val);
    }

    const bf16* vb = v + (size_t)bc * E_ * HW_;
    const uint32 ms0 = cvta_smem(Ms);
    const uint32 vs0 = cvta_smem(Vs);

#pragma unroll
    for (int pre = 0; pre < 2; pre++) {
        for (int p = tid; p < 400; p += 128) {
            const int e = p >> 3, h8 = (p & 7) << 3;
            cp16(vs0 + ((pre * 64 * SB_ + e * SB_ + h8) << 1),
                 vb + e * HW_ + z * 512 + pre * 64 + h8);
        }
        cp_commit();
    }

    const int rowA = ob + (lane & 15);
    const int colA = (lane >> 4) << 3;
    const int krow = lane & 15;
    const int hwadd = (lane >> 4) << 3;

    for (int t = 0; t < 8; t++) {
        const int buf = t & 1;
        const int hw0 = z * 512 + t * 64;
        if (t >= 7) cp_wait0(); else cp_wait1();
        __syncthreads();

        const uint32 vbase = vs0 + ((buf * 64 * SB_) << 1);
        float acc[8][4];
#pragma unroll
        for (int nt = 0; nt < 8; nt++)
#pragma unroll
            for (int r = 0; r < 4; r++) acc[nt][r] = 0.f;

#pragma unroll
        for (int ks = 0; ks < 4; ks++) {
            const int kc = 16 * ks;
            uint32 a0, a1, a2, a3;
            ldsm4(a0, a1, a2, a3, ms0 + ((rowA * SB_ + kc + colA) << 1));
            uint32 b0[8], b1[8];
#pragma unroll
            for (int p = 0; p < 4; p++)
                ldsm4t(b0[2 * p], b1[2 * p], b0[2 * p + 1], b1[2 * p + 1],
                       vbase + (((kc + krow) * SB_ + 16 * p + hwadd) << 1));
#pragma unroll
            for (int nt = 0; nt < 8; nt++)
                mma16(acc[nt], a0, a1, a2, a3, b0[nt], b1[nt]);
        }
        __syncthreads();

        if (t + 2 < 8) {
            for (int p = tid; p < 400; p += 128) {
                const int e = p >> 3, h8 = (p & 7) << 3;
                cp16(vs0 + ((buf * 64 * SB_ + e * SB_ + h8) << 1),
                     vb + e * HW_ + z * 512 + (t + 2) * 64 + h8);
            }
            cp_commit();
        }

        const int j0 = ob + g, j1 = ob + g + 8;
#pragma unroll
        for (int nt = 0; nt < 8; nt++) {
            const int hw = 8 * nt + 2 * tg;
            if (j0 < E_)
                *(bf162*)&tout[((size_t)(b * E_ + j0) * C_ + nh) * HW_ + hw0 + hw] =
                    __floats2bfloat162_rn(acc[nt][0], acc[nt][1]);
            if (j1 < E_)
                *(bf162*)&tout[((size_t)(b * E_ + j1) * C_ + nh) * HW_ + hw0 + hw] =
                    __floats2bfloat162_rn(acc[nt][2], acc[nt][3]);
        }
    }
}

// ============================================================
// Kernel 5: fused tail. 256 threads; weights loaded once per
// block; 4 hw-64 tiles per block with double-buffered T prefetch.
// ============================================================
__global__ void __launch_bounds__(256) tail_kernel(
    const bf16* __restrict__ T, const float* __restrict__ x,
    const float* __restrict__ bm1, const float* __restrict__ bm2,
    float* __restrict__ out)
{
    extern __shared__ bf16 smt[];
    bf16* Ws = smt;                // [3][64 o][SB_]
    bf16* D0 = smt + 3 * 64 * SB_; // [2 buf][64 c][SB_]
    const int be = blockIdx.y, tid = threadIdx.x;
    const int wid = tid >> 5, lane = tid & 31;
    const int g = lane >> 2, tg = lane & 3;
    const int ob = (wid & 3) * 16;
    const int nh0 = (wid >> 2) * 32;

    const uint32 ws0 = cvta_smem(Ws);
    const uint32 d0s = cvta_smem(D0);

    // group 0: weights + T tile 0 -> buf 0
    for (int it = tid; it < 1536; it += 256) {
        const int m = it >> 9, rem = it & 511, o = rem >> 3, s8 = (rem & 7) << 3;
        cp16(ws0 + ((m * 64 * SB_ + o * SB_ + s8) << 1), &g_wb[(3 + m) * 4096 + o * 64 + s8]);
    }
    const bf16* tbase = T + (size_t)be * SLAB_ + blockIdx.x * 256;
    for (int p = tid; p < 512; p += 256) {
        const int c = p >> 3, h8 = (p & 7) << 3;
        cp16(d0s + ((c * SB_ + h8) << 1), tbase + c * HW_ + h8);
    }
    cp_commit();

    const float* xbase = x + (size_t)be * SLAB_ + blockIdx.x * 256;
    const int rowA = ob + (lane & 15);
    const int colA = (lane >> 4) << 3;
    const int krow = lane & 15;
    const int hwadd = (lane >> 4) << 3;

    for (int t = 0; t < 4; t++) {
        const int buf = t & 1;
        const int hwt = t * 64;
        const uint32 ds0 = d0s + ((buf * 64 * SB_) << 1);
        bf16* Ds = D0 + buf * 64 * SB_;

        // prefetch T(t+1) into the other buffer (freed at end of tile t-1)
        if (t < 3) {
            for (int p = tid; p < 512; p += 256) {
                const int c = p >> 3, h8 = (p & 7) << 3;
                cp16(d0s + ((((1 - buf) * 64 * SB_) + c * SB_ + h8) << 1),
                     tbase + c * HW_ + hwt + 64 + h8);
            }
            cp_commit();
            cp_wait1();   // current tile's T (and weights on t=0) landed
        } else {
            cp_wait0();
        }

        // x residual
        float acc1[4][4];
#pragma unroll
        for (int nt = 0; nt < 4; nt++) {
            const int hw = hwt + nh0 + 8 * nt + 2 * tg;
            const float2 r0 = *(const float2*)(xbase + (size_t)(ob + g) * HW_ + hw);
            const float2 r1 = *(const float2*)(xbase + (size_t)(ob + g + 8) * HW_ + hw);
            acc1[nt][0] = r0.x; acc1[nt][1] = r0.y; acc1[nt][2] = r1.x; acc1[nt][3] = r1.y;
        }
        __syncthreads();

        // GEMM1: acc1 += Wo @ T
#pragma unroll
        for (int ks = 0; ks < 4; ks++) {
            const int kc = 16 * ks;
            uint32 a0, a1, a2, a3;
            ldsm4(a0, a1, a2, a3, ws0 + ((rowA * SB_ + kc + colA) << 1));
            uint32 b0[4], b1[4];
#pragma unroll
            for (int p = 0; p < 2; p++)
                ldsm4t(b0[2 * p], b1[2 * p], b0[2 * p + 1], b1[2 * p + 1],
                       ds0 + (((kc + krow) * SB_ + nh0 + 16 * p + hwadd) << 1));
#pragma unroll
            for (int nt = 0; nt < 4; nt++)
                mma16(acc1[nt], a0, a1, a2, a3, b0[nt], b1[nt]);
        }
        __syncthreads();

        // after -> Ds
#pragma unroll
        for (int nt = 0; nt < 4; nt++) {
            const int hw = nh0 + 8 * nt + 2 * tg;
            *(bf162*)&Ds[(ob + g) * SB_ + hw]     = __floats2bfloat162_rn(acc1[nt][0], acc1[nt][1]);
            *(bf162*)&Ds[(ob + g + 8) * SB_ + hw] = __floats2bfloat162_rn(acc1[nt][2], acc1[nt][3]);
        }
        __syncthreads();

        // GEMM2: h1 = gelu(Wm1 @ after + b1)
        float acc2[4][4];
        {
            const float bv0 = bm1[ob + g], bv1 = bm1[ob + g + 8];
#pragma unroll
            for (int nt = 0; nt < 4; nt++) {
                acc2[nt][0] = bv0; acc2[nt][1] = bv0; acc2[nt][2] = bv1; acc2[nt][3] = bv1;
            }
        }
#pragma unroll
        for (int ks = 0; ks < 4; ks++) {
            const int kc = 16 * ks;
            uint32 a0, a1, a2, a3;
            ldsm4(a0, a1, a2, a3, ws0 + ((64 * SB_ + rowA * SB_ + kc + colA) << 1));
            uint32 b0[4], b1[4];
#pragma unroll
            for (int p = 0; p < 2; p++)
                ldsm4t(b0[2 * p], b1[2 * p], b0[2 * p + 1], b1[2 * p + 1],
                       ds0 + (((kc + krow) * SB_ + nh0 + 16 * p + hwadd) << 1));
#pragma unroll
            for (int nt = 0; nt < 4; nt++)
                mma16(acc2[nt], a0, a1, a2, a3, b0[nt], b1[nt]);
        }
#pragma unroll
        for (int nt = 0; nt < 4; nt++)
#pragma unroll
            for (int r = 0; r < 4; r++) {
                const float v = acc2[nt][r];
                acc2[nt][r] = 0.5f * v * (1.f + erff(v * 0.7071067811865475f));
            }
        __syncthreads();

        // h1 -> Ds
#pragma unroll
        for (int nt = 0; nt < 4; nt++) {
            const int hw = nh0 + 8 * nt + 2 * tg;
            *(bf162*)&Ds[(ob + g) * SB_ + hw]     = __floats2bfloat162_rn(acc2[nt][0], acc2[nt][1]);
            *(bf162*)&Ds[(ob + g + 8) * SB_ + hw] = __floats2bfloat162_rn(acc2[nt][2], acc2[nt][3]);
        }
        __syncthreads();

        // GEMM3 (reuse acc2): out = acc1 + Wm2 @ h1 + b2
        {
            const float bv0 = bm2[ob + g], bv1 = bm2[ob + g + 8];
#pragma unroll
            for (int nt = 0; nt < 4; nt++) {
                acc2[nt][0] = bv0; acc2[nt][1] = bv0; acc2[nt][2] = bv1; acc2[nt][3] = bv1;
            }
        }
#pragma unroll
        for (int ks = 0; ks < 4; ks++) {
            const int kc = 16 * ks;
            uint32 a0, a1, a2, a3;
            ldsm4(a0, a1, a2, a3, ws0 + ((2 * 64 * SB_ + rowA * SB_ + kc + colA) << 1));
            uint32 b0[4], b1[4];
#pragma unroll
            for (int p = 0; p < 2; p++)
                ldsm4t(b0[2 * p], b1[2 * p], b0[2 * p + 1], b1[2 * p + 1],
                       ds0 + (((kc + krow) * SB_ + nh0 + 16 * p + hwadd) << 1));
#pragma unroll
            for (int nt = 0; nt < 4; nt++)
                mma16(acc2[nt], a0, a1, a2, a3, b0[nt], b1[nt]);
        }

        float* dst = out + (size_t)be * SLAB_ + blockIdx.x * 256;
#pragma unroll
        for (int nt = 0; nt < 4; nt++) {
            const int hw = hwt + nh0 + 8 * nt + 2 * tg;
            *(float2*)(dst + (size_t)(ob + g) * HW_ + hw) =
                make_float2(acc1[nt][0] + acc2[nt][0], acc1[nt][1] + acc2[nt][1]);
            *(float2*)(dst + (size_t)(ob + g + 8) * HW_ + hw) =
                make_float2(acc1[nt][2] + acc2[nt][2], acc1[nt][3] + acc2[nt][3]);
        }
        __syncthreads();   // buffer free before next iteration's prefetch target use
    }
}

// ============================================================
// Launch
// ============================================================
extern "C" void kernel_launch(void* const* d_in, const int* in_sizes, int n_in,
                              void* d_out, int out_size)
{
    const float* x    = (const float*)d_in[0];
    const float* lng  = (const float*)d_in[1];
    const float* lnb  = (const float*)d_in[2];
    const float* W_v  = (const float*)d_in[3];
    const float* W_k  = (const float*)d_in[4];
    const float* W_q  = (const float*)d_in[5];
    const float* W_o  = (const float*)d_in[6];
    const float* W_m1 = (const float*)d_in[7];
    const float* b_m1 = (const float*)d_in[8];
    const float* W_m2 = (const float*)d_in[9];
    const float* b_m2 = (const float*)d_in[10];
    float* out = (float*)d_out;

    bf16 *pv, *pk, *pq, *pt;
    float *pw, *pp;
    cudaGetSymbolAddress((void**)&pv, g_v);
    cudaGetSymbolAddress((void**)&pk, g_k);
    cudaGetSymbolAddress((void**)&pq, g_q);
    cudaGetSymbolAddress((void**)&pt, g_t);
    cudaGetSymbolAddress((void**)&pw, g_wts);
    cudaGetSymbolAddress((void**)&pp, g_part);

    const int smem_vkq  = (3 * 64 * SB_ + 64 * SB_) * 2;     // 36864
    const int smem_gram = (4 * 64 * SD_) * 2;                // 69632
    const int smem_mix  = (3 * 64 * SB_) * 2;                // 27648
    const int smem_tail = (3 * 64 * SB_ + 2 * 64 * SB_) * 2; // 46080
    cudaFuncSetAttribute(vkq_kernel,    cudaFuncAttributeMaxDynamicSharedMemorySize, smem_vkq);
    cudaFuncSetAttribute(gram_kernel,   cudaFuncAttributeMaxDynamicSharedMemorySize, smem_gram);
    cudaFuncSetAttribute(mixing_kernel, cudaFuncAttributeMaxDynamicSharedMemorySize, smem_mix);
    cudaFuncSetAttribute(tail_kernel,   cudaFuncAttributeMaxDynamicSharedMemorySize, smem_tail);

    setup_kernel<<<128, 256>>>(W_v, W_k, W_q, W_o, W_m1, W_m2, lng, lnb);

    ln_stats_kernel<<<BE_, 512>>>(x);

    vkq_kernel<<<dim3(HW_ / 256, BE_), 256, smem_vkq>>>(x, pv, pk, pq);

    gram_kernel<<<dim3(C_, B_, 4), 256, smem_gram>>>(pk, pq, pp);
    softmax_kernel<<<B_ * C_ / 4, 256>>>(pp, pw);

    mixing_kernel<<<dim3(C_, B_, 4), 128, smem_mix>>>(pv, pw, pt);

    tail_kernel<<<dim3(HW_ / 256, BE_), 256, smem_tail>>>(pt, x, b_m1, b_m2, out);
}